// round 9
// baseline (speedup 1.0000x reference)
#include <cuda_runtime.h>

// Problem constants (fixed by reference_code)
#define LSEQ 8192
#define BATCH 32
#define CIN 7
#define KER 73            // 512 // 7
#define DM 512
#define RT 16             // output rows per tile
#define SL 512            // rows per block strip
#define TILES (SL / RT)   // 32
#define WROWS (SL + RT + 1)    // 529 window rows: strip + 16 back + 1 fwd
#define WSRC (WROWS * CIN)     // 3703 staged x elements
#define XPITCH 532             // row pitch: >=529, 16B-aligned
#define NWMAIN (KER * 18)      // 1314 main weights
// weight smem block: [0,1314) conv_w, [1314,1332) left_w,
//                    [1332,1405) conv_b, [1405] left_b
#define WSM_TOTAL 1406

// out[b, n, c*73+k] = conv_b[k] + sum_{j=0..17} W2[k][j] * x[b, n+1-j, c]
//   W2[k][j] = conv_w[k][ (j/3)*3 + (2 - j%3) ]
// Conv position p = n-1+t contributes only if (after circular wrap) p >= 15.
// Interior rows 16..L-2 are unconditionally valid (fast path).

__global__ __launch_bounds__(512, 2)
void tokemb_kernel(const float* __restrict__ x,
                   const float* __restrict__ conv_w,
                   const float* __restrict__ conv_b,
                   const float* __restrict__ left_w,
                   const float* __restrict__ left_b,
                   float* __restrict__ out)
{
    const int d  = threadIdx.x;          // output channel 0..511
    const int s0 = blockIdx.x * SL;      // strip start row
    const int b  = blockIdx.y;

    const float* xb = x + (size_t)b * LSEQ * CIN;

    // x window, transposed: xs[c][row], row-contiguous -> LDS.128 tile reads.
    __shared__ float xs[CIN][XPITCH];
    // all weights + biases, staged cooperatively (coalesced LDG).
    __shared__ float wsm[WSM_TOTAL];

    // ---- Stage x FIRST (long-latency LDGs in flight early) --------------
    {
        const int gbase = (s0 - RT) * CIN;   // may be negative at strip 0
        int row = d / CIN;                   // one real div per thread
        int cc  = d - row * CIN;
        #pragma unroll
        for (int it = 0; it < 8; ++it) {     // ceil(3703/512) = 8
            const int idx = d + it * 512;
            if (idx < WSRC) {
                int g = gbase + idx;
                g = min(max(g, 0), LSEQ * CIN - 1);
                xs[cc][row] = xb[g];
            }
            // idx += 512 = 73*7 + 1  ->  row += 73, cc += 1 (wrap at 7)
            row += 73; cc += 1;
            if (cc == CIN) { cc = 0; row += 1; }
        }
    }

    // ---- Stage weights cooperatively (overlaps x-staging latency) -------
    {
        // conv_w: 1314 floats, coalesced
        for (int i = d; i < NWMAIN; i += 512) wsm[i] = conv_w[i];
        if (d < 18) wsm[NWMAIN + d] = left_w[d];
        if (d < KER) wsm[1332 + d] = conv_b[d];
        if (d == 0)  wsm[1405] = left_b[0];
    }
    __syncthreads();

    // ---- Per-thread weights/bias from smem (broadcast LDS) --------------
    const bool main_ch = (d < CIN * KER);            // d < 511
    const int  c    = main_ch ? (d / KER) : (CIN - 1);
    const int  wofs = main_ch ? ((d % KER) * 18) : NWMAIN;
    const float bias = main_ch ? wsm[1332 + (d % KER)] : wsm[1405];

    float w[18];
    #pragma unroll
    for (int j = 0; j < 18; ++j)
        w[j] = wsm[wofs + (j / 3) * 3 + 2 - (j % 3)];

    float* outp = out + ((size_t)(b * LSEQ + s0)) * DM + d;

    #pragma unroll 1
    for (int t = 0; t < TILES; ++t) {
        const int n0 = s0 + t * RT;
        float* op = outp + t * RT * DM;

        if ((n0 >= 16) && (n0 + RT <= LSEQ - 1)) {
            // xs[c] row l = global row s0-16+l; tile t reads rows t*16..t*16+32
            const float*  xcol = &xs[c][t * RT];
            const float4* xq   = reinterpret_cast<const float4*>(xcol);

            float acc[RT];

            // Value-outer fanout with vector loads. Tap j feeds output row
            // nl = i + j - 17; ascending i makes j==17 the first writer of
            // each acc -> fold bias init into it.
            #pragma unroll
            for (int g4 = 0; g4 < 8; ++g4) {
                const float4 q = xq[g4];             // LDS.128: i = 4g..4g+3
                const float qv[4] = {q.x, q.y, q.z, q.w};
                #pragma unroll
                for (int c4 = 0; c4 < 4; ++c4) {
                    const int   i  = 4 * g4 + c4;
                    const float xv = qv[c4];
                    #pragma unroll
                    for (int j = 0; j < 18; ++j) {
                        const int nl = i + j - 17;
                        if (nl >= 0 && nl < RT) {
                            if (j == 17) acc[nl] = fmaf(w[17], xv, bias);
                            else         acc[nl] = fmaf(w[j],  xv, acc[nl]);
                        }
                    }
                }
            }
            {   // window value i = 32: only tap j=0 (nl = 15) remains
                acc[RT - 1] = fmaf(w[0], xcol[32], acc[RT - 1]);
            }

            #pragma unroll
            for (int nl = 0; nl < RT; ++nl)
                op[nl * DM] = acc[nl];
        } else {
            // Generic path: explicit wrap + validity per conv tap. Only the
            // first and last tile of each sequence land here.
            for (int nl = 0; nl < RT; ++nl) {
                const int n = n0 + nl;
                float acc = bias;
                #pragma unroll
                for (int tt = 0; tt < 3; ++tt) {
                    int p = n - 1 + tt;
                    if (p < 0)      p += LSEQ;   // circular pad left
                    if (p >= LSEQ)  p -= LSEQ;   // circular pad right
                    if (p >= 15) {               // delay-embedding validity
                        #pragma unroll
                        for (int m = 0; m < 6; ++m)
                            acc = fmaf(w[3 * m + 2 - tt],
                                       xb[(p - 3 * m) * CIN + c], acc);
                    }
                }
                op[nl * DM] = acc;
            }
        }
    }
}

extern "C" void kernel_launch(void* const* d_in, const int* in_sizes, int n_in,
                              void* d_out, int out_size)
{
    const float* x      = (const float*)d_in[0];
    const float* conv_w = (const float*)d_in[1];
    const float* conv_b = (const float*)d_in[2];
    const float* left_w = (const float*)d_in[3];
    const float* left_b = (const float*)d_in[4];
    float* out = (float*)d_out;

    dim3 grid(LSEQ / SL, BATCH);   // (16, 32) = 512 blocks
    tokemb_kernel<<<grid, 512>>>(x, conv_w, conv_b, left_w, left_b, out);
}

// round 10
// speedup vs baseline: 1.0865x; 1.0865x over previous
#include <cuda_runtime.h>

// Problem constants (fixed by reference_code)
#define LSEQ 8192
#define BATCH 32
#define CIN 7
#define KER 73            // 512 // 7
#define DM 512
#define RT 8              // output rows per tile (small => 3 CTAs/SM resident)
#define SL 256            // rows per block strip (proven R8 shape)
#define TILES (SL / RT)   // 32
#define WROWS (SL + 16 + 1)    // 273 window rows: strip + 16 back + 1 fwd
#define WSRC (WROWS * CIN)     // 1911 staged elements
#define XPITCH 276             // row pitch: >=273, 16B-aligned

// out[b, n, c*73+k] = conv_b[k] + sum_{j=0..17} W2[k][j] * x[b, n+1-j, c]
//   W2[k][j] = conv_w[k][ (j/3)*3 + (2 - j%3) ]
// Conv position p = n-1+t contributes only if (after circular wrap) p >= 15.
// Interior rows 16..L-2 are unconditionally valid (fast path).
//
// __launch_bounds__(512, 3): cap regs at 42 so 3 CTAs (48 warps) fit per SM.
// The extra resident CTA exists purely to cover LDS/STG stall bursts that
// phase-aligned warps at 2 CTAs/SM could not hide (issue was 83%).

__global__ __launch_bounds__(512, 3)
void tokemb_kernel(const float* __restrict__ x,
                   const float* __restrict__ conv_w,
                   const float* __restrict__ conv_b,
                   const float* __restrict__ left_w,
                   const float* __restrict__ left_b,
                   float* __restrict__ out)
{
    const int d  = threadIdx.x;          // output channel 0..511
    const int s0 = blockIdx.x * SL;      // strip start row
    const int b  = blockIdx.y;

    // Per-thread channel / weights / bias (loaded ONCE per block)
    const bool main_ch = (d < CIN * KER);            // d < 511
    const int  c    = main_ch ? (d / KER) : (CIN - 1);
    const float* wsrc = main_ch ? (conv_w + (d % KER) * 18) : left_w;
    const float bias  = main_ch ? conv_b[d % KER] : left_b[0];

    float w[18];
    #pragma unroll
    for (int j = 0; j < 18; ++j)
        w[j] = wsrc[(j / 3) * 3 + 2 - (j % 3)];

    const float* xb = x + (size_t)b * LSEQ * CIN;

    // Stage x[b, s0-16 .. s0+SL, :] TRANSPOSED: xs[c][row], row-contiguous so
    // tile reads vectorize to LDS.128. Index-clamped; clamped junk rows are
    // only consumed by slow-path tiles, which bypass smem entirely.
    __shared__ float xs[CIN][XPITCH];
    {
        const int gbase = (s0 - 16) * CIN;   // may be negative at strip 0
        for (int idx = d; idx < WSRC; idx += 512) {
            int g = gbase + idx;
            g = min(max(g, 0), LSEQ * CIN - 1);
            const int row = idx / CIN;
            const int cc  = idx - row * CIN;
            xs[cc][row] = xb[g];
        }
    }
    __syncthreads();

    float* outp = out + ((size_t)(b * LSEQ + s0)) * DM + d;

    #pragma unroll 1
    for (int t = 0; t < TILES; ++t) {
        const int n0 = s0 + t * RT;
        float* op = outp + t * RT * DM;

        if ((n0 >= 16) && (n0 + RT <= LSEQ - 1)) {
            // xs[c] row l = global row s0-16+l; tile t reads rows t*8..t*8+24
            const float*  xcol = &xs[c][t * RT];            // t*8 % 4 == 0
            const float4* xq   = reinterpret_cast<const float4*>(xcol);

            float acc[RT];

            // Value-outer fanout with vector loads. Tap j feeds output row
            // nl = i + j - 17; ascending i makes j==17 the first writer of
            // each acc -> fold bias init into it (i == nl, j == 17).
            #pragma unroll
            for (int g4 = 0; g4 < 6; ++g4) {
                const float4 q = xq[g4];             // LDS.128: i = 4g..4g+3
                const float qv[4] = {q.x, q.y, q.z, q.w};
                #pragma unroll
                for (int c4 = 0; c4 < 4; ++c4) {
                    const int   i  = 4 * g4 + c4;
                    const float xv = qv[c4];
                    #pragma unroll
                    for (int j = 0; j < 18; ++j) {
                        const int nl = i + j - 17;
                        if (nl >= 0 && nl < RT) {
                            if (j == 17) acc[nl] = fmaf(w[17], xv, bias);
                            else         acc[nl] = fmaf(w[j],  xv, acc[nl]);
                        }
                    }
                }
            }
            {   // window value i = 24: only tap j=0 (nl = 7) remains
                acc[RT - 1] = fmaf(w[0], xcol[24], acc[RT - 1]);
            }

            #pragma unroll
            for (int nl = 0; nl < RT; ++nl)
                op[nl * DM] = acc[nl];
        } else {
            // Generic path: explicit wrap + validity per conv tap. Only the
            // first two and last tiles of each sequence land here.
            for (int nl = 0; nl < RT; ++nl) {
                const int n = n0 + nl;
                float acc = bias;
                #pragma unroll
                for (int tt = 0; tt < 3; ++tt) {
                    int p = n - 1 + tt;
                    if (p < 0)      p += LSEQ;   // circular pad left
                    if (p >= LSEQ)  p -= LSEQ;   // circular pad right
                    if (p >= 15) {               // delay-embedding validity
                        #pragma unroll
                        for (int m = 0; m < 6; ++m)
                            acc = fmaf(w[3 * m + 2 - tt],
                                       xb[(p - 3 * m) * CIN + c], acc);
                    }
                }
                op[nl * DM] = acc;
            }
        }
    }
}

extern "C" void kernel_launch(void* const* d_in, const int* in_sizes, int n_in,
                              void* d_out, int out_size)
{
    const float* x      = (const float*)d_in[0];
    const float* conv_w = (const float*)d_in[1];
    const float* conv_b = (const float*)d_in[2];
    const float* left_w = (const float*)d_in[3];
    const float* left_b = (const float*)d_in[4];
    float* out = (float*)d_out;

    dim3 grid(LSEQ / SL, BATCH);   // (32, 32) = 1024 blocks
    tokemb_kernel<<<grid, 512>>>(x, conv_w, conv_b, left_w, left_b, out);
}